// round 7
// baseline (speedup 1.0000x reference)
#include <cuda_runtime.h>
#include <cuda_bf16.h>
#include <cstdint>

#define NN 100000
#define NE 600000
#define NR 3
#define NL 3
#define DIM 128
#define BN_EPS 1e-5f

#if defined(__CUDA_ARCH_FEAT_SM103_ALL) || defined(__CUDA_ARCH_FEAT_SM100_ALL) || \
    defined(__CUDA_ARCH_FEAT_SM101_ALL) || \
    (defined(__CUDA_ARCH_FAMILY_SPECIFIC__) && (__CUDA_ARCH_FAMILY_SPECIFIC__ >= 1000)) || \
    (defined(__CUDA_ARCH_SPECIFIC__) && (__CUDA_ARCH_SPECIFIC__ >= 1000))
#define HAS_TCGEN05 1
#else
#define HAS_TCGEN05 0
#endif

// ---------------- scratch ----------------
__device__ __align__(16) float g_hA[(size_t)NN * DIM];
__device__ __align__(16) float g_hB[(size_t)NN * DIM];
__device__ __align__(16) float g_dinv_o[NR * NN];
__device__ __align__(16) float g_dinv_i[NR * NN];
__device__ __align__(16) int g_cnt_in[NR * NN];
__device__ __align__(16) int g_cnt_out[NR * NN];
__device__ __align__(16) int g_cursor[NR * NN];
__device__ __align__(16) int g_excl[NR * NN];
__device__ __align__(16) int g_bsum[512];
__device__ __align__(16) int g_srcidx[NR * NE];
__device__ __align__(16) float g_stats3[3 * 2 * DIM];
__device__ __align__(16) uint8_t g_Wbf[12 * 65536];   // 9 conv + 3 fc: [hi 32KB | lo 32KB] swizzled
__device__ __align__(16) float g_fceff[NL * DIM];

// ---------------- PTX helpers ----------------
__device__ __forceinline__ uint32_t smem_u32(const void* p) {
    uint32_t a;
    asm("{ .reg .u64 t; cvta.to.shared.u64 t, %1; cvt.u32.u64 %0, t; }" : "=r"(a) : "l"(p));
    return a;
}

#if HAS_TCGEN05
__device__ __forceinline__ uint32_t elect_one() {
    uint32_t pred;
    asm volatile("{\n\t.reg .pred p;\n\telect.sync _|p, 0xFFFFFFFF;\n\tselp.b32 %0, 1, 0, p;\n\t}" : "=r"(pred));
    return pred;
}
#define MBARRIER_INIT(addr, cnt) \
    asm volatile("mbarrier.init.shared.b64 [%0], %1;" :: "r"((uint32_t)(addr)), "r"((uint32_t)(cnt)) : "memory")
__device__ __forceinline__ void mbar_wait(uint32_t mbar, uint32_t parity) {
    asm volatile(
        "{\n\t.reg .pred P;\n\t"
        "WL_%=:\n\t"
        "mbarrier.try_wait.parity.acquire.cta.shared::cta.b64 P, [%0], %1, 0x989680;\n\t"
        "@P bra.uni WD_%=;\n\t"
        "bra.uni WL_%=;\n\t"
        "WD_%=:\n\t}"
        :: "r"(mbar), "r"(parity) : "memory");
}
#define TCGEN05_ALLOC(smem_addr, n) \
    asm volatile("tcgen05.alloc.cta_group::1.sync.aligned.shared::cta.b32 [%0], %1;" \
                 :: "r"((uint32_t)(smem_addr)), "r"((uint32_t)(n)) : "memory")
#define TCGEN05_DEALLOC(tmem, n) \
    asm volatile("tcgen05.dealloc.cta_group::1.sync.aligned.b32 %0, %1;" :: "r"(tmem), "r"((uint32_t)(n)))
#define TCGEN05_COMMIT(mbar) \
    asm volatile("tcgen05.commit.cta_group::1.mbarrier::arrive::one.shared::cluster.b64 [%0];" \
                 :: "r"((uint32_t)(mbar)) : "memory")
#define TCGEN05_WAIT_LD() asm volatile("tcgen05.wait::ld.sync.aligned;" ::: "memory")
#define TCGEN05_FENCE_AFTER() asm volatile("tcgen05.fence::after_thread_sync;" ::: "memory")
#define FENCE_ASYNC_SHARED() asm volatile("fence.proxy.async.shared::cta;" ::: "memory")

#define TCGEN05_LD_32X32B_X32(r, tmem_addr) \
    asm volatile( \
        "tcgen05.ld.sync.aligned.32x32b.x32.b32 " \
        "{%0, %1, %2, %3, %4, %5, %6, %7, " \
        " %8, %9, %10, %11, %12, %13, %14, %15, " \
        " %16, %17, %18, %19, %20, %21, %22, %23, " \
        " %24, %25, %26, %27, %28, %29, %30, %31}, [%32];" \
        : "=r"((r)[0]),  "=r"((r)[1]),  "=r"((r)[2]),  "=r"((r)[3]), \
          "=r"((r)[4]),  "=r"((r)[5]),  "=r"((r)[6]),  "=r"((r)[7]), \
          "=r"((r)[8]),  "=r"((r)[9]),  "=r"((r)[10]), "=r"((r)[11]), \
          "=r"((r)[12]), "=r"((r)[13]), "=r"((r)[14]), "=r"((r)[15]), \
          "=r"((r)[16]), "=r"((r)[17]), "=r"((r)[18]), "=r"((r)[19]), \
          "=r"((r)[20]), "=r"((r)[21]), "=r"((r)[22]), "=r"((r)[23]), \
          "=r"((r)[24]), "=r"((r)[25]), "=r"((r)[26]), "=r"((r)[27]), \
          "=r"((r)[28]), "=r"((r)[29]), "=r"((r)[30]), "=r"((r)[31]) \
        : "r"(tmem_addr))

static constexpr uint64_t SMEM_DESC_BASE_SW128 =
    (uint64_t(2) << 61) | (uint64_t(1) << 46) | (uint64_t(64) << 32) | (uint64_t(1) << 16);
#define MAKE_SMEM_DESC(base_addr) (SMEM_DESC_BASE_SW128 | ((uint64_t)((base_addr) >> 4) & 0x3FFF))

__device__ __forceinline__ void mma_f16_ss(uint32_t d, uint64_t a, uint64_t b, uint32_t idesc, int acc) {
    asm volatile(
        "{\n\t.reg .pred p;\n\tsetp.ne.u32 p, %4, 0;\n\t"
        "tcgen05.mma.cta_group::1.kind::f16 [%0], %1, %2, %3, {%5, %5, %5, %5}, p;\n\t}"
        :: "r"(d), "l"(a), "l"(b), "r"(idesc), "r"(acc), "r"(0u) : "memory");
}
#define MMA_IDESC 0x8200490u

// one K=128 MMA sweep (8 k-steps) over a 32KB A image and 32KB B image
__device__ __forceinline__ void mma_pass(uint32_t d, uint64_t a, uint64_t b, bool first) {
#pragma unroll
    for (int s = 0; s < 8; s++) {
        uint64_t o = (s < 4) ? (uint64_t)(s * 2) : (uint64_t)(1024 + (s - 4) * 2);
        mma_f16_ss(d, a + o, b + o, MMA_IDESC, !(first && s == 0));
    }
}
#endif  // HAS_TCGEN05

// Blocked SW128 atom layout for a 128x128 bf16 tile.
__host__ __device__ __forceinline__ uint32_t tile_off(int row, int col) {
    uint32_t off = (uint32_t)(((row >> 3) + ((col >> 6) << 4)) << 10) | ((row & 7) << 7) | ((col & 63) << 1);
    return off ^ ((off >> 3) & 0x70);
}

// bf16 hi/lo split of a float4, store swizzled to two smem images
__device__ __forceinline__ void split_store(char* base_hi, char* base_lo, uint32_t off, float4 v) {
    __nv_bfloat162 h01 = __floats2bfloat162_rn(v.x, v.y);
    __nv_bfloat162 h23 = __floats2bfloat162_rn(v.z, v.w);
    float lx = v.x - __bfloat162float(h01.x);
    float ly = v.y - __bfloat162float(h01.y);
    float lz = v.z - __bfloat162float(h23.x);
    float lw = v.w - __bfloat162float(h23.y);
    __nv_bfloat162 l01 = __floats2bfloat162_rn(lx, ly);
    __nv_bfloat162 l23 = __floats2bfloat162_rn(lz, lw);
    uint2 hv, lv;
    hv.x = *(uint32_t*)&h01; hv.y = *(uint32_t*)&h23;
    lv.x = *(uint32_t*)&l01; lv.y = *(uint32_t*)&l23;
    *(uint2*)(base_hi + off) = hv;
    *(uint2*)(base_lo + off) = lv;
}

// ---------------- prep kernels ----------------
__global__ void __launch_bounds__(256) k_zeroprep(int* a, int* b, int* c, float* stats, int n) {
    int i = blockIdx.x * 256 + threadIdx.x;
    if (i < n) { a[i] = 0; b[i] = 0; c[i] = 0; }
    if (i < 3 * 2 * DIM) stats[i] = 0.f;
}
__global__ void __launch_bounds__(256) k_cnt(const int* __restrict__ edges,
                                             int* __restrict__ cnt_out, int* __restrict__ cnt_in) {
    int i = blockIdx.x * 256 + threadIdx.x;
    if (i >= NR * NE) return;
    int r = i / NE;
    int e = i - r * NE;
    int s = edges[(size_t)(r * 2 + 0) * NE + e];
    int d = edges[(size_t)(r * 2 + 1) * NE + e];
    atomicAdd(&cnt_out[r * NN + s], 1);
    atomicAdd(&cnt_in[r * NN + d], 1);
}
__global__ void __launch_bounds__(256) k_dinv(const int* __restrict__ cnt_out, const int* __restrict__ cnt_in,
                                              float* __restrict__ dinv_o, float* __restrict__ dinv_i) {
    int i = blockIdx.x * 256 + threadIdx.x;
    if (i >= NR * NN) return;
    dinv_o[i] = rsqrtf(fmaxf((float)cnt_out[i], 1.f));
    dinv_i[i] = rsqrtf(fmaxf((float)cnt_in[i], 1.f));
}
__global__ void __launch_bounds__(1024) k_scan1(const int* __restrict__ cnt, int* __restrict__ excl,
                                                int* __restrict__ bsum, int N) {
    int i = blockIdx.x * 1024 + threadIdx.x;
    int lane = threadIdx.x & 31, warp = threadIdx.x >> 5;
    int x = (i < N) ? cnt[i] : 0;
    int v = x;
#pragma unroll
    for (int o = 1; o < 32; o <<= 1) { int y = __shfl_up_sync(~0u, v, o); if (lane >= o) v += y; }
    __shared__ int ws[32];
    if (lane == 31) ws[warp] = v;
    __syncthreads();
    if (warp == 0) {
        int w = ws[lane];
#pragma unroll
        for (int o = 1; o < 32; o <<= 1) { int y = __shfl_up_sync(~0u, w, o); if (lane >= o) w += y; }
        ws[lane] = w;
    }
    __syncthreads();
    int wexcl = (warp == 0) ? 0 : ws[warp - 1];
    if (i < N) excl[i] = wexcl + v - x;
    if (threadIdx.x == 1023) bsum[blockIdx.x] = ws[31];
}
__global__ void __launch_bounds__(512) k_scan2(int* __restrict__ bsum, int nb) {
    __shared__ int s[512];
    int tid = threadIdx.x;
    int v = (tid < nb) ? bsum[tid] : 0;
    s[tid] = v;
    __syncthreads();
    for (int o = 1; o < 512; o <<= 1) {
        int y = (tid >= o) ? s[tid - o] : 0;
        __syncthreads();
        s[tid] += y;
        __syncthreads();
    }
    if (tid < nb) bsum[tid] = s[tid] - v;
}
__global__ void __launch_bounds__(1024) k_scan3(int* __restrict__ excl, const int* __restrict__ bsum, int N) {
    int i = blockIdx.x * 1024 + threadIdx.x;
    if (i < N) excl[i] += bsum[blockIdx.x];
}
__global__ void __launch_bounds__(256) k_place(const int* __restrict__ edges, const int* __restrict__ excl,
                                               int* __restrict__ cursor, int* __restrict__ srcidx) {
    int i = blockIdx.x * 256 + threadIdx.x;
    if (i >= NR * NE) return;
    int r = i / NE;
    int e = i - r * NE;
    int s = edges[(size_t)(r * 2 + 0) * NE + e];
    int d = edges[(size_t)(r * 2 + 1) * NE + e];
    int pos = atomicAdd(&cursor[r * NN + d], 1);
    srcidx[excl[r * NN + d] + pos] = s;
}
__global__ void __launch_bounds__(256) k_wprep(const float* __restrict__ convW,
                                               const float* __restrict__ fcW,
                                               uint8_t* __restrict__ wbf) {
    int idx = blockIdx.x * 256 + threadIdx.x;
    if (idx >= 12 * 16384) return;
    int w = idx >> 14;
    int e = idx & 16383;
    int k = e >> 7, n = e & 127;
    const float* W = (w < 9) ? (convW + (size_t)w * 16384) : (fcW + (size_t)(w - 9) * 16384);
    float v = W[e];
    __nv_bfloat16 hi = __float2bfloat16(v);
    __nv_bfloat16 lo = __float2bfloat16(v - __bfloat162float(hi));
    uint32_t off = tile_off(n, k);
    *(__nv_bfloat16*)(wbf + (size_t)w * 65536 + off) = hi;
    *(__nv_bfloat16*)(wbf + (size_t)w * 65536 + 32768 + off) = lo;
}
__global__ void __launch_bounds__(128) k_bprep(const float* __restrict__ conv_b,
                                               const float* __restrict__ fc_W,
                                               const float* __restrict__ fc_b,
                                               float* __restrict__ fceff) {
    __shared__ float bs[DIM];
    int l = blockIdx.x, n = threadIdx.x;
    bs[n] = conv_b[(size_t)(l * 3 + 0) * DIM + n] + conv_b[(size_t)(l * 3 + 1) * DIM + n] +
            conv_b[(size_t)(l * 3 + 2) * DIM + n];
    __syncthreads();
    float acc = fc_b[(size_t)l * DIM + n];
    for (int k = 0; k < DIM; k++) acc += bs[k] * fc_W[(size_t)l * DIM * DIM + (size_t)k * DIM + n];
    fceff[(size_t)l * DIM + n] = acc;
}

// ---------------- fused layer kernel ----------------
// Per 128-node tile: gather 3 relation tiles from Hin (BN affine + dinv folds),
// 3 conv MMAs accumulate agg in TMEM, TMEM->SMEM bf16 split, FC MMA,
// epilogue: +bias, relu, write Hout, BN-stat atomics.
#define L_TMEM 0
#define L_MB 8                          // 4 mbarriers at 8,16,24,32
#define L_BNS 64
#define L_BNB 576
#define L_A 2048                        // 3 x (hi 32KB | lo 32KB)
#define L_W (L_A + 3 * 65536)           // 198656: 32KB W half-buffer
#define L_TOTAL (L_W + 32768)           // 231424

template <bool BN>
__global__ void __launch_bounds__(256, 1) k_layer(const float4* __restrict__ Hin,
                                                  const uint8_t* __restrict__ wconv,  // 3 x 64KB
                                                  const uint8_t* __restrict__ wfc,    // 64KB
                                                  const float* __restrict__ fcb,
                                                  const float* __restrict__ stats_in,
                                                  const float* __restrict__ gamma,
                                                  const float* __restrict__ beta,
                                                  const int* __restrict__ srcidx,
                                                  const int* __restrict__ excl,
                                                  const int* __restrict__ cnt,
                                                  const float* __restrict__ dinv_o,
                                                  const float* __restrict__ dinv_i,
                                                  float* __restrict__ Hout,
                                                  float* __restrict__ stats_out) {
    extern __shared__ char sm[];
    int tid = threadIdx.x, wid = tid >> 5, lid = tid & 31;
    int row0 = blockIdx.x * 128;

    float* bns = (float*)(sm + L_BNS);
    float* bnb = (float*)(sm + L_BNB);
    if (tid < DIM) {
        if (BN) {
            float mean = stats_in[tid] * (1.f / NN);
            float var = stats_in[DIM + tid] * (1.f / NN) - mean * mean;
            float inv = rsqrtf(var + BN_EPS);
            float sc = gamma[tid] * inv;
            bns[tid] = sc;
            bnb[tid] = beta[tid] - mean * sc;
        } else {
            bns[tid] = 1.f;
            bnb[tid] = 0.f;
        }
    }

#if HAS_TCGEN05
    uint32_t smb = smem_u32(sm);
    if (tid == 0) {
#pragma unroll
        for (int j = 0; j < 4; j++) MBARRIER_INIT(smb + L_MB + 8 * j, 1);
    }
    if (wid == 0) { TCGEN05_ALLOC(smb + L_TMEM, 256); }
    __syncthreads();

    // ---- gather phase: each warp builds 16 rows of all 3 relation tiles ----
    for (int i = 0; i < 16; i++) {
        int lrow = wid * 16 + i;
        int node = row0 + lrow;
        bool ok = node < NN;
        float S[NR][4];
        float sig[NR];
#pragma unroll
        for (int r = 0; r < NR; r++) {
            S[r][0] = S[r][1] = S[r][2] = S[r][3] = 0.f;
            sig[r] = 0.f;
        }
        if (ok) {
#pragma unroll
            for (int r = 0; r < NR; r++) {
                int n = cnt[r * NN + node];
                int base = excl[r * NN + node];
                for (int c0 = 0; c0 < n; c0 += 32) {
                    int j = c0 + lid;
                    int sl = (j < n) ? srcidx[base + j] : 0;
                    float dl = (j < n) ? dinv_o[r * NN + sl] : 0.f;
                    int lim = min(32, n - c0);
                    int ii = 0;
                    for (; ii + 1 < lim; ii += 2) {
                        int s0 = __shfl_sync(~0u, sl, ii);
                        int s1 = __shfl_sync(~0u, sl, ii + 1);
                        float w0 = __shfl_sync(~0u, dl, ii);
                        float w1 = __shfl_sync(~0u, dl, ii + 1);
                        float4 v0 = Hin[(size_t)s0 * 32 + lid];
                        float4 v1 = Hin[(size_t)s1 * 32 + lid];
                        S[r][0] += w0 * v0.x + w1 * v1.x;
                        S[r][1] += w0 * v0.y + w1 * v1.y;
                        S[r][2] += w0 * v0.z + w1 * v1.z;
                        S[r][3] += w0 * v0.w + w1 * v1.w;
                        sig[r] += w0 + w1;
                    }
                    if (ii < lim) {
                        int s0 = __shfl_sync(~0u, sl, ii);
                        float w0 = __shfl_sync(~0u, dl, ii);
                        float4 v0 = Hin[(size_t)s0 * 32 + lid];
                        S[r][0] += w0 * v0.x;
                        S[r][1] += w0 * v0.y;
                        S[r][2] += w0 * v0.z;
                        S[r][3] += w0 * v0.w;
                        sig[r] += w0;
                    }
                }
            }
        }
        int c = lid * 4;
        uint32_t off = tile_off(lrow, c);
#pragma unroll
        for (int r = 0; r < NR; r++) {
            float di = ok ? dinv_i[r * NN + node] : 0.f;
            float4 t;
            t.x = di * (bns[c + 0] * S[r][0] + bnb[c + 0] * sig[r]);
            t.y = di * (bns[c + 1] * S[r][1] + bnb[c + 1] * sig[r]);
            t.z = di * (bns[c + 2] * S[r][2] + bnb[c + 2] * sig[r]);
            t.w = di * (bns[c + 3] * S[r][3] + bnb[c + 3] * sig[r]);
            split_store(sm + L_A + r * 65536, sm + L_A + r * 65536 + 32768, off, t);
        }
    }
    FENCE_ASYNC_SHARED();
    __syncthreads();

    uint32_t tmem;
    asm volatile("ld.shared.b32 %0, [%1];" : "=r"(tmem) : "r"(smb + L_TMEM));
    bool issuer = (wid == 0) && elect_one();
    uint64_t bdesc = MAKE_SMEM_DESC(smb + L_W);
    float4* Wsm = (float4*)(sm + L_W);
    int k = 0;

    // ---- conv MMAs: per relation, hi-W passes then lo-W pass, into tmem[0..127] ----
#pragma unroll
    for (int r = 0; r < NR; r++) {
        uint64_t aH = MAKE_SMEM_DESC(smb + L_A + r * 65536);
        uint64_t aL = MAKE_SMEM_DESC(smb + L_A + r * 65536 + 32768);
        // W_r hi
        {
            const float4* src = (const float4*)(wconv + (size_t)r * 65536);
#pragma unroll
            for (int q = 0; q < 8; q++) Wsm[tid + q * 256] = src[tid + q * 256];
        }
        FENCE_ASYNC_SHARED();
        __syncthreads();
        if (issuer) {
            mma_pass(tmem, aH, bdesc, r == 0);
            mma_pass(tmem, aL, bdesc, false);
            TCGEN05_COMMIT(smb + L_MB + 8 * (k & 3));
        }
        mbar_wait(smb + L_MB + 8 * (k & 3), k >> 2);
        k++;
        // W_r lo
        {
            const float4* src = (const float4*)(wconv + (size_t)r * 65536 + 32768);
#pragma unroll
            for (int q = 0; q < 8; q++) Wsm[tid + q * 256] = src[tid + q * 256];
        }
        FENCE_ASYNC_SHARED();
        __syncthreads();
        if (issuer) {
            mma_pass(tmem, aH, bdesc, false);
            TCGEN05_COMMIT(smb + L_MB + 8 * (k & 3));
        }
        mbar_wait(smb + L_MB + 8 * (k & 3), k >> 2);
        k++;
    }

    // ---- TMEM agg -> SMEM bf16 hi/lo (reuse A0), FC MMA into tmem[128..255] ----
    TCGEN05_FENCE_AFTER();
    int rb = (wid & 3) * 32 + lid;
    int cb = (wid >> 2) * 64;
#pragma unroll
    for (int hh = 0; hh < 2; hh++) {
        uint32_t dr[32];
        TCGEN05_LD_32X32B_X32(dr, tmem + cb + hh * 32);
        TCGEN05_WAIT_LD();
#pragma unroll
        for (int j = 0; j < 8; j++) {
            float4 v;
            v.x = __uint_as_float(dr[4 * j + 0]);
            v.y = __uint_as_float(dr[4 * j + 1]);
            v.z = __uint_as_float(dr[4 * j + 2]);
            v.w = __uint_as_float(dr[4 * j + 3]);
            split_store(sm + L_A, sm + L_A + 32768, tile_off(rb, cb + hh * 32 + j * 4), v);
        }
    }
    // fc W hi (Wbuf free: all conv MMAs waited)
    {
        const float4* src = (const float4*)wfc;
#pragma unroll
        for (int q = 0; q < 8; q++) Wsm[tid + q * 256] = src[tid + q * 256];
    }
    FENCE_ASYNC_SHARED();
    __syncthreads();
    uint64_t aH0 = MAKE_SMEM_DESC(smb + L_A);
    uint64_t aL0 = MAKE_SMEM_DESC(smb + L_A + 32768);
    if (issuer) {
        mma_pass(tmem + 128, aH0, bdesc, true);
        mma_pass(tmem + 128, aL0, bdesc, false);
        TCGEN05_COMMIT(smb + L_MB + 8 * (k & 3));
    }
    mbar_wait(smb + L_MB + 8 * (k & 3), k >> 2);
    k++;
    {
        const float4* src = (const float4*)(wfc + 32768);
#pragma unroll
        for (int q = 0; q < 8; q++) Wsm[tid + q * 256] = src[tid + q * 256];
    }
    FENCE_ASYNC_SHARED();
    __syncthreads();
    if (issuer) {
        mma_pass(tmem + 128, aH0, bdesc, false);
        TCGEN05_COMMIT(smb + L_MB + 8 * (k & 3));
    }
    mbar_wait(smb + L_MB + 8 * (k & 3), k >> 2);
    k++;
    TCGEN05_FENCE_AFTER();

    // ---- epilogue: bias + relu + write Hout + BN stats ----
    int grow = row0 + rb;
    bool ok = grow < NN;
#pragma unroll
    for (int hh = 0; hh < 2; hh++) {
        uint32_t dr[32];
        TCGEN05_LD_32X32B_X32(dr, tmem + 128 + cb + hh * 32);
        TCGEN05_WAIT_LD();
        float v[32];
#pragma unroll
        for (int j = 0; j < 32; j++) {
            int col = cb + hh * 32 + j;
            float x = __uint_as_float(dr[j]) + fcb[col];
            x = fmaxf(x, 0.f);
            v[j] = ok ? x : 0.f;
        }
        if (ok) {
            float* op = Hout + (size_t)grow * DIM + cb + hh * 32;
#pragma unroll
            for (int j = 0; j < 8; j++)
                *(float4*)(op + 4 * j) = make_float4(v[4 * j], v[4 * j + 1], v[4 * j + 2], v[4 * j + 3]);
        }
#pragma unroll
        for (int j = 0; j < 32; j++) {
            float s = v[j];
            float q = v[j] * v[j];
#pragma unroll
            for (int o = 16; o; o >>= 1) {
                s += __shfl_xor_sync(~0u, s, o);
                q += __shfl_xor_sync(~0u, q, o);
            }
            if (lid == 0) {
                int col = cb + hh * 32 + j;
                atomicAdd(&stats_out[col], s);
                atomicAdd(&stats_out[DIM + col], q);
            }
        }
    }

    __syncthreads();
    if (wid == 0) TCGEN05_DEALLOC(tmem, 256);

#else  // ---------------- fallback (never runs on sm_103a; correctness only) ----------------
    float* Af = (float*)(sm + L_A);
    float* AGG = (float*)(sm + L_A + 65536);
    float* Wf = (float*)(sm + L_A + 131072);
    __syncthreads();
    for (int i = tid; i < 16384; i += 256) AGG[i] = 0.f;
    __syncthreads();

    for (int r = 0; r < NR; r++) {
        for (int i = 0; i < 16; i++) {
            int lrow = wid * 16 + i;
            int node = row0 + lrow;
            bool ok = node < NN;
            float S0 = 0.f, S1 = 0.f, S2 = 0.f, S3 = 0.f, sig = 0.f;
            if (ok) {
                int n = cnt[r * NN + node];
                int base = excl[r * NN + node];
                for (int c0 = 0; c0 < n; c0 += 32) {
                    int j = c0 + lid;
                    int sl = (j < n) ? srcidx[base + j] : 0;
                    float dl = (j < n) ? dinv_o[r * NN + sl] : 0.f;
                    int lim = min(32, n - c0);
                    for (int ii = 0; ii < lim; ii++) {
                        int s0 = __shfl_sync(~0u, sl, ii);
                        float w0 = __shfl_sync(~0u, dl, ii);
                        float4 v0 = Hin[(size_t)s0 * 32 + lid];
                        S0 += w0 * v0.x; S1 += w0 * v0.y; S2 += w0 * v0.z; S3 += w0 * v0.w;
                        sig += w0;
                    }
                }
            }
            float di = ok ? dinv_i[r * NN + node] : 0.f;
            int c = lid * 4;
            Af[lrow * 128 + c + 0] = di * (bns[c + 0] * S0 + bnb[c + 0] * sig);
            Af[lrow * 128 + c + 1] = di * (bns[c + 1] * S1 + bnb[c + 1] * sig);
            Af[lrow * 128 + c + 2] = di * (bns[c + 2] * S2 + bnb[c + 2] * sig);
            Af[lrow * 128 + c + 3] = di * (bns[c + 3] * S3 + bnb[c + 3] * sig);
        }
        for (int i = tid; i < 16384; i += 256) {
            int kk = i >> 7, n = i & 127;
            uint32_t off = tile_off(n, kk);
            const uint8_t* Wr = wconv + (size_t)r * 65536;
            Wf[i] = __bfloat162float(*(const __nv_bfloat16*)(Wr + off)) +
                    __bfloat162float(*(const __nv_bfloat16*)(Wr + 32768 + off));
        }
        __syncthreads();
        int row = tid >> 1, cbb = (tid & 1) * 64;
        for (int c = 0; c < 64; c++) {
            float acc = 0.f;
            for (int kk = 0; kk < 128; kk++) acc += Af[row * 128 + kk] * Wf[kk * 128 + cbb + c];
            AGG[row * 128 + cbb + c] += acc;
        }
        __syncthreads();
    }
    for (int i = tid; i < 16384; i += 256) Af[i] = AGG[i];
    for (int i = tid; i < 16384; i += 256) {
        int kk = i >> 7, n = i & 127;
        uint32_t off = tile_off(n, kk);
        Wf[i] = __bfloat162float(*(const __nv_bfloat16*)(wfc + off)) +
                __bfloat162float(*(const __nv_bfloat16*)(wfc + 32768 + off));
    }
    __syncthreads();
    {
        int row = tid >> 1, cbb = (tid & 1) * 64;
        int grow = row0 + row;
        for (int c = 0; c < 64; c++) {
            float acc = fcb[cbb + c];
            for (int kk = 0; kk < 128; kk++) acc += Af[row * 128 + kk] * Wf[kk * 128 + cbb + c];
            acc = fmaxf(acc, 0.f);
            if (grow < NN) {
                Hout[(size_t)grow * DIM + cbb + c] = acc;
                atomicAdd(&stats_out[cbb + c], acc);
                atomicAdd(&stats_out[DIM + cbb + c], acc * acc);
            }
        }
    }
#endif
}

// ---------------- final BatchNorm normalize ----------------
__global__ void __launch_bounds__(256) k_bnnorm(const float* __restrict__ h,
                                                const float* __restrict__ stats,
                                                const float* __restrict__ gamma,
                                                const float* __restrict__ beta,
                                                float* __restrict__ out) {
    int i = blockIdx.x * 256 + threadIdx.x;
    if (i >= NN * DIM / 4) return;
    int c = (i & 31) * 4;
    float4 v = *(const float4*)(h + (size_t)i * 4);
    float vin[4] = {v.x, v.y, v.z, v.w};
    float o[4];
#pragma unroll
    for (int j = 0; j < 4; j++) {
        float mean = stats[c + j] * (1.f / NN);
        float var = stats[DIM + c + j] * (1.f / NN) - mean * mean;
        float inv = rsqrtf(var + BN_EPS);
        o[j] = (vin[j] - mean) * inv * gamma[c + j] + beta[c + j];
    }
    *(float4*)(out + (size_t)i * 4) = make_float4(o[0], o[1], o[2], o[3]);
}

// ---------------- launch ----------------
extern "C" void kernel_launch(void* const* d_in, const int* in_sizes, int n_in,
                              void* d_out, int out_size) {
    const float* x      = (const float*)d_in[0];
    const int*   edges  = (const int*)d_in[1];
    const float* conv_W = (const float*)d_in[2];
    const float* conv_b = (const float*)d_in[3];
    const float* fc_W   = (const float*)d_in[4];
    const float* fc_b   = (const float*)d_in[5];
    const float* gamma  = (const float*)d_in[6];
    const float* beta   = (const float*)d_in[7];
    float* out = (float*)d_out;

    float *hA, *hB, *dinv_o, *dinv_i, *stats3, *fceff;
    int *cnt_in, *cnt_out, *cursor, *excl, *bsum, *srcidx;
    uint8_t* wbf;
    cudaGetSymbolAddress((void**)&hA, g_hA);
    cudaGetSymbolAddress((void**)&hB, g_hB);
    cudaGetSymbolAddress((void**)&dinv_o, g_dinv_o);
    cudaGetSymbolAddress((void**)&dinv_i, g_dinv_i);
    cudaGetSymbolAddress((void**)&cnt_in, g_cnt_in);
    cudaGetSymbolAddress((void**)&cnt_out, g_cnt_out);
    cudaGetSymbolAddress((void**)&cursor, g_cursor);
    cudaGetSymbolAddress((void**)&excl, g_excl);
    cudaGetSymbolAddress((void**)&bsum, g_bsum);
    cudaGetSymbolAddress((void**)&srcidx, g_srcidx);
    cudaGetSymbolAddress((void**)&stats3, g_stats3);
    cudaGetSymbolAddress((void**)&wbf, g_Wbf);
    cudaGetSymbolAddress((void**)&fceff, g_fceff);

    cudaFuncSetAttribute(k_layer<false>, cudaFuncAttributeMaxDynamicSharedMemorySize, L_TOTAL);
    cudaFuncSetAttribute(k_layer<true>, cudaFuncAttributeMaxDynamicSharedMemorySize, L_TOTAL);

    const int NSC = NR * NN;
    const int NB1 = (NSC + 1023) / 1024;
    const int LGRID = (NN + 127) / 128;   // 782

    // ---- prep ----
    k_wprep<<<(12 * 16384 + 255) / 256, 256>>>(conv_W, fc_W, wbf);
    k_bprep<<<NL, 128>>>(conv_b, fc_W, fc_b, fceff);
    k_zeroprep<<<(NSC + 255) / 256, 256>>>(cnt_in, cnt_out, cursor, stats3, NSC);
    k_cnt<<<(NR * NE + 255) / 256, 256>>>(edges, cnt_out, cnt_in);
    k_dinv<<<(NSC + 255) / 256, 256>>>(cnt_out, cnt_in, dinv_o, dinv_i);
    k_scan1<<<NB1, 1024>>>(cnt_in, excl, bsum, NSC);
    k_scan2<<<1, 512>>>(bsum, NB1);
    k_scan3<<<NB1, 1024>>>(excl, bsum, NSC);
    k_place<<<(NR * NE + 255) / 256, 256>>>(edges, excl, cursor, srcidx);

    // ---- layers ----
    k_layer<false><<<LGRID, 256, L_TOTAL>>>(
        (const float4*)x, wbf, wbf + (size_t)9 * 65536, fceff,
        nullptr, nullptr, nullptr,
        srcidx, excl, cnt_in, dinv_o, dinv_i, hA, stats3);
    k_layer<true><<<LGRID, 256, L_TOTAL>>>(
        (const float4*)hA, wbf + (size_t)3 * 65536, wbf + (size_t)10 * 65536, fceff + DIM,
        stats3, gamma, beta,
        srcidx, excl, cnt_in, dinv_o, dinv_i, hB, stats3 + 2 * DIM);
    k_layer<true><<<LGRID, 256, L_TOTAL>>>(
        (const float4*)hB, wbf + (size_t)6 * 65536, wbf + (size_t)11 * 65536, fceff + 2 * DIM,
        stats3 + 2 * DIM, gamma + DIM, beta + DIM,
        srcidx, excl, cnt_in, dinv_o, dinv_i, hA, stats3 + 4 * DIM);
    k_bnnorm<<<(NN * DIM / 4 + 255) / 256, 256>>>(hA, stats3 + 4 * DIM,
                                                  gamma + 2 * DIM, beta + 2 * DIM, out);
}

// round 8
// speedup vs baseline: 1.4548x; 1.4548x over previous
#include <cuda_runtime.h>
#include <cuda_bf16.h>
#include <cstdint>

#define NN 100000
#define NE 600000
#define NR 3
#define NL 3
#define DIM 128
#define BN_EPS 1e-5f

#if defined(__CUDA_ARCH_FEAT_SM103_ALL) || defined(__CUDA_ARCH_FEAT_SM100_ALL) || \
    defined(__CUDA_ARCH_FEAT_SM101_ALL) || \
    (defined(__CUDA_ARCH_FAMILY_SPECIFIC__) && (__CUDA_ARCH_FAMILY_SPECIFIC__ >= 1000)) || \
    (defined(__CUDA_ARCH_SPECIFIC__) && (__CUDA_ARCH_SPECIFIC__ >= 1000))
#define HAS_TCGEN05 1
#else
#define HAS_TCGEN05 0
#endif

// ---------------- scratch ----------------
__device__ __align__(16) float g_hA[(size_t)NN * DIM];
__device__ __align__(16) float g_hB[(size_t)NN * DIM];
__device__ __align__(16) float g_t[(size_t)NR * NN * DIM];   // gathered per-relation tiles
__device__ __align__(16) float g_dinv_o[NR * NN];
__device__ __align__(16) float g_dinv_i[NR * NN];
__device__ __align__(16) int g_cnt_in[NR * NN];
__device__ __align__(16) int g_cnt_out[NR * NN];
__device__ __align__(16) int g_cursor[NR * NN];
__device__ __align__(16) int g_excl[NR * NN];
__device__ __align__(16) int g_bsum[512];
__device__ __align__(16) int g_srcidx[NR * NE];
__device__ __align__(16) float g_stats3[3 * 2 * DIM];
__device__ __align__(16) uint8_t g_Wbf[12 * 65536];   // 9 conv + 3 fc: [hi 32KB | lo 32KB] swizzled
__device__ __align__(16) float g_fceff[NL * DIM];

// ---------------- PTX helpers ----------------
__device__ __forceinline__ uint32_t smem_u32(const void* p) {
    uint32_t a;
    asm("{ .reg .u64 t; cvta.to.shared.u64 t, %1; cvt.u32.u64 %0, t; }" : "=r"(a) : "l"(p));
    return a;
}

#if HAS_TCGEN05
__device__ __forceinline__ uint32_t elect_one() {
    uint32_t pred;
    asm volatile("{\n\t.reg .pred p;\n\telect.sync _|p, 0xFFFFFFFF;\n\tselp.b32 %0, 1, 0, p;\n\t}" : "=r"(pred));
    return pred;
}
#define MBARRIER_INIT(addr, cnt) \
    asm volatile("mbarrier.init.shared.b64 [%0], %1;" :: "r"((uint32_t)(addr)), "r"((uint32_t)(cnt)) : "memory")
__device__ __forceinline__ void mbar_wait(uint32_t mbar, uint32_t parity) {
    asm volatile(
        "{\n\t.reg .pred P;\n\t"
        "WL_%=:\n\t"
        "mbarrier.try_wait.parity.acquire.cta.shared::cta.b64 P, [%0], %1, 0x989680;\n\t"
        "@P bra.uni WD_%=;\n\t"
        "bra.uni WL_%=;\n\t"
        "WD_%=:\n\t}"
        :: "r"(mbar), "r"(parity) : "memory");
}
#define TCGEN05_ALLOC(smem_addr, n) \
    asm volatile("tcgen05.alloc.cta_group::1.sync.aligned.shared::cta.b32 [%0], %1;" \
                 :: "r"((uint32_t)(smem_addr)), "r"((uint32_t)(n)) : "memory")
#define TCGEN05_DEALLOC(tmem, n) \
    asm volatile("tcgen05.dealloc.cta_group::1.sync.aligned.b32 %0, %1;" :: "r"(tmem), "r"((uint32_t)(n)))
#define TCGEN05_COMMIT(mbar) \
    asm volatile("tcgen05.commit.cta_group::1.mbarrier::arrive::one.shared::cluster.b64 [%0];" \
                 :: "r"((uint32_t)(mbar)) : "memory")
#define TCGEN05_WAIT_LD() asm volatile("tcgen05.wait::ld.sync.aligned;" ::: "memory")
#define TCGEN05_FENCE_AFTER() asm volatile("tcgen05.fence::after_thread_sync;" ::: "memory")
#define FENCE_ASYNC_SHARED() asm volatile("fence.proxy.async.shared::cta;" ::: "memory")

#define TCGEN05_LD_32X32B_X32(r, tmem_addr) \
    asm volatile( \
        "tcgen05.ld.sync.aligned.32x32b.x32.b32 " \
        "{%0, %1, %2, %3, %4, %5, %6, %7, " \
        " %8, %9, %10, %11, %12, %13, %14, %15, " \
        " %16, %17, %18, %19, %20, %21, %22, %23, " \
        " %24, %25, %26, %27, %28, %29, %30, %31}, [%32];" \
        : "=r"((r)[0]),  "=r"((r)[1]),  "=r"((r)[2]),  "=r"((r)[3]), \
          "=r"((r)[4]),  "=r"((r)[5]),  "=r"((r)[6]),  "=r"((r)[7]), \
          "=r"((r)[8]),  "=r"((r)[9]),  "=r"((r)[10]), "=r"((r)[11]), \
          "=r"((r)[12]), "=r"((r)[13]), "=r"((r)[14]), "=r"((r)[15]), \
          "=r"((r)[16]), "=r"((r)[17]), "=r"((r)[18]), "=r"((r)[19]), \
          "=r"((r)[20]), "=r"((r)[21]), "=r"((r)[22]), "=r"((r)[23]), \
          "=r"((r)[24]), "=r"((r)[25]), "=r"((r)[26]), "=r"((r)[27]), \
          "=r"((r)[28]), "=r"((r)[29]), "=r"((r)[30]), "=r"((r)[31]) \
        : "r"(tmem_addr))

static constexpr uint64_t SMEM_DESC_BASE_SW128 =
    (uint64_t(2) << 61) | (uint64_t(1) << 46) | (uint64_t(64) << 32) | (uint64_t(1) << 16);
#define MAKE_SMEM_DESC(base_addr) (SMEM_DESC_BASE_SW128 | ((uint64_t)((base_addr) >> 4) & 0x3FFF))

__device__ __forceinline__ void mma_f16_ss(uint32_t d, uint64_t a, uint64_t b, uint32_t idesc, int acc) {
    asm volatile(
        "{\n\t.reg .pred p;\n\tsetp.ne.u32 p, %4, 0;\n\t"
        "tcgen05.mma.cta_group::1.kind::f16 [%0], %1, %2, %3, {%5, %5, %5, %5}, p;\n\t}"
        :: "r"(d), "l"(a), "l"(b), "r"(idesc), "r"(acc), "r"(0u) : "memory");
}
#define MMA_IDESC 0x8200490u

__device__ __forceinline__ void mma_pass(uint32_t d, uint64_t a, uint64_t b, bool first) {
#pragma unroll
    for (int s = 0; s < 8; s++) {
        uint64_t o = (s < 4) ? (uint64_t)(s * 2) : (uint64_t)(1024 + (s - 4) * 2);
        mma_f16_ss(d, a + o, b + o, MMA_IDESC, !(first && s == 0));
    }
}
#endif  // HAS_TCGEN05

// Blocked SW128 atom layout for a 128x128 bf16 tile.
__host__ __device__ __forceinline__ uint32_t tile_off(int row, int col) {
    uint32_t off = (uint32_t)(((row >> 3) + ((col >> 6) << 4)) << 10) | ((row & 7) << 7) | ((col & 63) << 1);
    return off ^ ((off >> 3) & 0x70);
}

__device__ __forceinline__ void split_store(char* base_hi, char* base_lo, uint32_t off, float4 v) {
    __nv_bfloat162 h01 = __floats2bfloat162_rn(v.x, v.y);
    __nv_bfloat162 h23 = __floats2bfloat162_rn(v.z, v.w);
    float lx = v.x - __bfloat162float(h01.x);
    float ly = v.y - __bfloat162float(h01.y);
    float lz = v.z - __bfloat162float(h23.x);
    float lw = v.w - __bfloat162float(h23.y);
    __nv_bfloat162 l01 = __floats2bfloat162_rn(lx, ly);
    __nv_bfloat162 l23 = __floats2bfloat162_rn(lz, lw);
    uint2 hv, lv;
    hv.x = *(uint32_t*)&h01; hv.y = *(uint32_t*)&h23;
    lv.x = *(uint32_t*)&l01; lv.y = *(uint32_t*)&l23;
    *(uint2*)(base_hi + off) = hv;
    *(uint2*)(base_lo + off) = lv;
}

// ---------------- prep kernels ----------------
__global__ void __launch_bounds__(256) k_zeroprep(int* a, int* b, int* c, float* stats, int n) {
    int i = blockIdx.x * 256 + threadIdx.x;
    if (i < n) { a[i] = 0; b[i] = 0; c[i] = 0; }
    if (i < 3 * 2 * DIM) stats[i] = 0.f;
}
__global__ void __launch_bounds__(256) k_cnt(const int* __restrict__ edges,
                                             int* __restrict__ cnt_out, int* __restrict__ cnt_in) {
    int i = blockIdx.x * 256 + threadIdx.x;
    if (i >= NR * NE) return;
    int r = i / NE;
    int e = i - r * NE;
    int s = edges[(size_t)(r * 2 + 0) * NE + e];
    int d = edges[(size_t)(r * 2 + 1) * NE + e];
    atomicAdd(&cnt_out[r * NN + s], 1);
    atomicAdd(&cnt_in[r * NN + d], 1);
}
__global__ void __launch_bounds__(256) k_dinv(const int* __restrict__ cnt_out, const int* __restrict__ cnt_in,
                                              float* __restrict__ dinv_o, float* __restrict__ dinv_i) {
    int i = blockIdx.x * 256 + threadIdx.x;
    if (i >= NR * NN) return;
    dinv_o[i] = rsqrtf(fmaxf((float)cnt_out[i], 1.f));
    dinv_i[i] = rsqrtf(fmaxf((float)cnt_in[i], 1.f));
}
__global__ void __launch_bounds__(1024) k_scan1(const int* __restrict__ cnt, int* __restrict__ excl,
                                                int* __restrict__ bsum, int N) {
    int i = blockIdx.x * 1024 + threadIdx.x;
    int lane = threadIdx.x & 31, warp = threadIdx.x >> 5;
    int x = (i < N) ? cnt[i] : 0;
    int v = x;
#pragma unroll
    for (int o = 1; o < 32; o <<= 1) { int y = __shfl_up_sync(~0u, v, o); if (lane >= o) v += y; }
    __shared__ int ws[32];
    if (lane == 31) ws[warp] = v;
    __syncthreads();
    if (warp == 0) {
        int w = ws[lane];
#pragma unroll
        for (int o = 1; o < 32; o <<= 1) { int y = __shfl_up_sync(~0u, w, o); if (lane >= o) w += y; }
        ws[lane] = w;
    }
    __syncthreads();
    int wexcl = (warp == 0) ? 0 : ws[warp - 1];
    if (i < N) excl[i] = wexcl + v - x;
    if (threadIdx.x == 1023) bsum[blockIdx.x] = ws[31];
}
__global__ void __launch_bounds__(512) k_scan2(int* __restrict__ bsum, int nb) {
    __shared__ int s[512];
    int tid = threadIdx.x;
    int v = (tid < nb) ? bsum[tid] : 0;
    s[tid] = v;
    __syncthreads();
    for (int o = 1; o < 512; o <<= 1) {
        int y = (tid >= o) ? s[tid - o] : 0;
        __syncthreads();
        s[tid] += y;
        __syncthreads();
    }
    if (tid < nb) bsum[tid] = s[tid] - v;
}
__global__ void __launch_bounds__(1024) k_scan3(int* __restrict__ excl, const int* __restrict__ bsum, int N) {
    int i = blockIdx.x * 1024 + threadIdx.x;
    if (i < N) excl[i] += bsum[blockIdx.x];
}
__global__ void __launch_bounds__(256) k_place(const int* __restrict__ edges, const int* __restrict__ excl,
                                               int* __restrict__ cursor, int* __restrict__ srcidx) {
    int i = blockIdx.x * 256 + threadIdx.x;
    if (i >= NR * NE) return;
    int r = i / NE;
    int e = i - r * NE;
    int s = edges[(size_t)(r * 2 + 0) * NE + e];
    int d = edges[(size_t)(r * 2 + 1) * NE + e];
    int pos = atomicAdd(&cursor[r * NN + d], 1);
    srcidx[excl[r * NN + d] + pos] = s;
}
__global__ void __launch_bounds__(256) k_wprep(const float* __restrict__ convW,
                                               const float* __restrict__ fcW,
                                               uint8_t* __restrict__ wbf) {
    int idx = blockIdx.x * 256 + threadIdx.x;
    if (idx >= 12 * 16384) return;
    int w = idx >> 14;
    int e = idx & 16383;
    int k = e >> 7, n = e & 127;
    const float* W = (w < 9) ? (convW + (size_t)w * 16384) : (fcW + (size_t)(w - 9) * 16384);
    float v = W[e];
    __nv_bfloat16 hi = __float2bfloat16(v);
    __nv_bfloat16 lo = __float2bfloat16(v - __bfloat162float(hi));
    uint32_t off = tile_off(n, k);
    *(__nv_bfloat16*)(wbf + (size_t)w * 65536 + off) = hi;
    *(__nv_bfloat16*)(wbf + (size_t)w * 65536 + 32768 + off) = lo;
}
__global__ void __launch_bounds__(128) k_bprep(const float* __restrict__ conv_b,
                                               const float* __restrict__ fc_W,
                                               const float* __restrict__ fc_b,
                                               float* __restrict__ fceff) {
    __shared__ float bs[DIM];
    int l = blockIdx.x, n = threadIdx.x;
    bs[n] = conv_b[(size_t)(l * 3 + 0) * DIM + n] + conv_b[(size_t)(l * 3 + 1) * DIM + n] +
            conv_b[(size_t)(l * 3 + 2) * DIM + n];
    __syncthreads();
    float acc = fc_b[(size_t)l * DIM + n];
    for (int k = 0; k < DIM; k++) acc += bs[k] * fc_W[(size_t)l * DIM * DIM + (size_t)k * DIM + n];
    fceff[(size_t)l * DIM + n] = acc;
}

// ---------------- gather (high occupancy, no smem): t_r[d] = dinv_i_r[d]*(bns⊙Σ w_s h[s] + bnb·Σ w_s) ----------------
template <bool BN>
__global__ void __launch_bounds__(256) k_gath(const float4* __restrict__ Hin,
                                              const int* __restrict__ srcidx,
                                              const int* __restrict__ excl,
                                              const int* __restrict__ cnt,
                                              const float* __restrict__ dinv_o,
                                              const float* __restrict__ dinv_i,
                                              const float* __restrict__ stats_in,
                                              const float* __restrict__ gamma,
                                              const float* __restrict__ beta,
                                              float* __restrict__ t) {
    int node = (blockIdx.x * 256 + threadIdx.x) >> 5;
    int lane = threadIdx.x & 31;
    if (node >= NN) return;

    int c = lane * 4;
    float bns[4], bnb[4];
#pragma unroll
    for (int j = 0; j < 4; j++) {
        if (BN) {
            float mean = stats_in[c + j] * (1.f / NN);
            float var = stats_in[DIM + c + j] * (1.f / NN) - mean * mean;
            float inv = rsqrtf(var + BN_EPS);
            float sc = gamma[c + j] * inv;
            bns[j] = sc;
            bnb[j] = beta[c + j] - mean * sc;
        } else {
            bns[j] = 1.f;
            bnb[j] = 0.f;
        }
    }

#pragma unroll
    for (int r = 0; r < NR; r++) {
        int n = cnt[r * NN + node];
        int base = excl[r * NN + node];
        float S0 = 0.f, S1 = 0.f, S2 = 0.f, S3 = 0.f, sig = 0.f;
        for (int c0 = 0; c0 < n; c0 += 32) {
            int j = c0 + lane;
            int sl = (j < n) ? srcidx[base + j] : 0;
            float dl = (j < n) ? dinv_o[r * NN + sl] : 0.f;
            int lim = min(32, n - c0);
            int ii = 0;
            for (; ii + 1 < lim; ii += 2) {
                int s0 = __shfl_sync(~0u, sl, ii);
                int s1 = __shfl_sync(~0u, sl, ii + 1);
                float w0 = __shfl_sync(~0u, dl, ii);
                float w1 = __shfl_sync(~0u, dl, ii + 1);
                float4 v0 = Hin[(size_t)s0 * 32 + lane];
                float4 v1 = Hin[(size_t)s1 * 32 + lane];
                S0 += w0 * v0.x + w1 * v1.x;
                S1 += w0 * v0.y + w1 * v1.y;
                S2 += w0 * v0.z + w1 * v1.z;
                S3 += w0 * v0.w + w1 * v1.w;
                sig += w0 + w1;
            }
            if (ii < lim) {
                int s0 = __shfl_sync(~0u, sl, ii);
                float w0 = __shfl_sync(~0u, dl, ii);
                float4 v0 = Hin[(size_t)s0 * 32 + lane];
                S0 += w0 * v0.x; S1 += w0 * v0.y; S2 += w0 * v0.z; S3 += w0 * v0.w;
                sig += w0;
            }
        }
        float di = dinv_i[r * NN + node];
        float4 o;
        o.x = di * (bns[0] * S0 + bnb[0] * sig);
        o.y = di * (bns[1] * S1 + bnb[1] * sig);
        o.z = di * (bns[2] * S2 + bnb[2] * sig);
        o.w = di * (bns[3] * S3 + bnb[3] * sig);
        *(float4*)(t + ((size_t)r * NN + node) * DIM + c) = o;
    }
}

// ---------------- GEMM kernel: agg = Σ_r t_r @ W_r in TMEM, then h' = relu(agg @ Wfc + b), BN stats ----------------
#define M_TMEM 0
#define M_MB 8                       // 4 mbarriers at 8,16,24,32
#define M_A 1024                     // hi 32KB | lo 32KB
#define M_W (M_A + 65536)            // 2 x 64KB double buffer
#define M_TOTAL (M_W + 131072)       // 197632

__global__ void __launch_bounds__(256, 1) k_mm(const float* __restrict__ t,
                                               const uint8_t* __restrict__ wconv,  // 3 x 64KB
                                               const uint8_t* __restrict__ wfc,    // 64KB
                                               const float* __restrict__ fcb,
                                               float* __restrict__ Hout,
                                               float* __restrict__ stats_out) {
    extern __shared__ char sm[];
    int tid = threadIdx.x, wid = tid >> 5, lid = tid & 31;
    int row0 = blockIdx.x * 128;

#if HAS_TCGEN05
    uint32_t smb = smem_u32(sm);
    if (tid == 0) {
#pragma unroll
        for (int j = 0; j < 4; j++) MBARRIER_INIT(smb + M_MB + 8 * j, 1);
    }
    if (wid == 0) { TCGEN05_ALLOC(smb + M_TMEM, 256); }
    __syncthreads();

    uint32_t tmem;
    asm volatile("ld.shared.b32 %0, [%1];" : "=r"(tmem) : "r"(smb + M_TMEM));
    bool issuer = (wid == 0) && elect_one();
    uint64_t aH = MAKE_SMEM_DESC(smb + M_A);
    uint64_t aL = MAKE_SMEM_DESC(smb + M_A + 32768);

    // helper lambdas (compiled inline)
    auto loadW = [&](const uint8_t* src8, int buf) {
        const float4* src = (const float4*)src8;
        float4* dst = (float4*)(sm + M_W + buf * 65536);
#pragma unroll
        for (int q = 0; q < 16; q++) dst[tid + q * 256] = src[tid + q * 256];
    };
    auto loadA = [&](const float* tr) {
#pragma unroll
        for (int g = 0; g < 2; g++) {
            float4 buf[8];
#pragma unroll
            for (int b = 0; b < 8; b++) {
                int i = g * 2048 + b * 256 + tid;
                int grow = row0 + (i >> 5);
                buf[b] = (grow < NN) ? *(const float4*)(tr + (size_t)grow * DIM + (i & 31) * 4)
                                     : make_float4(0.f, 0.f, 0.f, 0.f);
            }
#pragma unroll
            for (int b = 0; b < 8; b++) {
                int i = g * 2048 + b * 256 + tid;
                split_store(sm + M_A, sm + M_A + 32768, tile_off(i >> 5, (i & 31) * 4), buf[b]);
            }
        }
    };

    // stage W0 + A(t0)
    loadW(wconv, 0);
    loadA(t);
    FENCE_ASYNC_SHARED();
    __syncthreads();

    // conv MMAs: r=0..2, W double-buffered, A reloaded after each commit-wait
#pragma unroll
    for (int r = 0; r < NR; r++) {
        int buf = r & 1;
        if (issuer) {
            uint64_t bH = MAKE_SMEM_DESC(smb + M_W + buf * 65536);
            uint64_t bL = MAKE_SMEM_DESC(smb + M_W + buf * 65536 + 32768);
            mma_pass(tmem, aH, bH, r == 0);
            mma_pass(tmem, aH, bL, false);
            mma_pass(tmem, aL, bH, false);
            TCGEN05_COMMIT(smb + M_MB + 8 * r);
        }
        // stage next W into the other buffer while MMA runs
        if (r < 2) loadW(wconv + (size_t)(r + 1) * 65536, buf ^ 1);
        else       loadW(wfc, buf ^ 1);
        // wait MMA r (frees A buffer)
        mbar_wait(smb + M_MB + 8 * r, 0);
        if (r < 2) loadA(t + (size_t)(r + 1) * NN * DIM);
        FENCE_ASYNC_SHARED();
        __syncthreads();
    }

    // TMEM agg -> SMEM bf16 hi/lo (into A buffer)
    TCGEN05_FENCE_AFTER();
    int rb = (wid & 3) * 32 + lid;
    int cb = (wid >> 2) * 64;
#pragma unroll
    for (int hh = 0; hh < 2; hh++) {
        uint32_t dr[32];
        TCGEN05_LD_32X32B_X32(dr, tmem + cb + hh * 32);
        TCGEN05_WAIT_LD();
#pragma unroll
        for (int j = 0; j < 8; j++) {
            float4 v;
            v.x = __uint_as_float(dr[4 * j + 0]);
            v.y = __uint_as_float(dr[4 * j + 1]);
            v.z = __uint_as_float(dr[4 * j + 2]);
            v.w = __uint_as_float(dr[4 * j + 3]);
            split_store(sm + M_A, sm + M_A + 32768, tile_off(rb, cb + hh * 32 + j * 4), v);
        }
    }
    FENCE_ASYNC_SHARED();
    __syncthreads();

    // FC MMA (Wfc staged in buf1 during r=2)
    if (issuer) {
        uint64_t bH = MAKE_SMEM_DESC(smb + M_W + 65536);
        uint64_t bL = MAKE_SMEM_DESC(smb + M_W + 65536 + 32768);
        mma_pass(tmem + 128, aH, bH, true);
        mma_pass(tmem + 128, aH, bL, false);
        mma_pass(tmem + 128, aL, bH, false);
        TCGEN05_COMMIT(smb + M_MB + 24);
    }
    mbar_wait(smb + M_MB + 24, 0);
    TCGEN05_FENCE_AFTER();

    // epilogue: bias + relu + write Hout + BN stats
    int grow = row0 + rb;
    bool ok = grow < NN;
#pragma unroll
    for (int hh = 0; hh < 2; hh++) {
        uint32_t dr[32];
        TCGEN05_LD_32X32B_X32(dr, tmem + 128 + cb + hh * 32);
        TCGEN05_WAIT_LD();
        float v[32];
#pragma unroll
        for (int j = 0; j < 32; j++) {
            int col = cb + hh * 32 + j;
            float x = __uint_as_float(dr[j]) + fcb[col];
            x = fmaxf(x, 0.f);
            v[j] = ok ? x : 0.f;
        }
        if (ok) {
            float* op = Hout + (size_t)grow * DIM + cb + hh * 32;
#pragma unroll
            for (int j = 0; j < 8; j++)
                *(float4*)(op + 4 * j) = make_float4(v[4 * j], v[4 * j + 1], v[4 * j + 2], v[4 * j + 3]);
        }
#pragma unroll
        for (int j = 0; j < 32; j++) {
            float s = v[j];
            float q = v[j] * v[j];
#pragma unroll
            for (int o = 16; o; o >>= 1) {
                s += __shfl_xor_sync(~0u, s, o);
                q += __shfl_xor_sync(~0u, q, o);
            }
            if (lid == 0) {
                int col = cb + hh * 32 + j;
                atomicAdd(&stats_out[col], s);
                atomicAdd(&stats_out[DIM + col], q);
            }
        }
    }

    __syncthreads();
    if (wid == 0) TCGEN05_DEALLOC(tmem, 256);

#else  // ---------------- fallback: scalar (non-'a' target; correctness only) ----------------
    float* Af = (float*)sm;                  // 64KB fp32 tile
    float* AGG = (float*)(sm + 65536);
    float* Wf = (float*)(sm + 131072);
    for (int i = tid; i < 16384; i += 256) AGG[i] = 0.f;
    __syncthreads();

    for (int r = 0; r < NR; r++) {
        const float* tr = t + (size_t)r * NN * DIM;
        for (int i = tid; i < 4096; i += 256) {
            int grow = row0 + (i >> 5);
            float4 v = (grow < NN) ? *(const float4*)(tr + (size_t)grow * DIM + (i & 31) * 4)
                                   : make_float4(0.f, 0.f, 0.f, 0.f);
            *(float4*)(Af + (size_t)(i >> 5) * DIM + (i & 31) * 4) = v;
        }
        for (int i = tid; i < 16384; i += 256) {
            int kk = i >> 7, n = i & 127;
            uint32_t off = tile_off(n, kk);
            const uint8_t* Wr = wconv + (size_t)r * 65536;
            Wf[i] = __bfloat162float(*(const __nv_bfloat16*)(Wr + off)) +
                    __bfloat162float(*(const __nv_bfloat16*)(Wr + 32768 + off));
        }
        __syncthreads();
        int row = tid >> 1, cbb = (tid & 1) * 64;
        for (int c = 0; c < 64; c++) {
            float acc = 0.f;
            for (int kk = 0; kk < 128; kk++) acc += Af[row * 128 + kk] * Wf[kk * 128 + cbb + c];
            AGG[row * 128 + cbb + c] += acc;
        }
        __syncthreads();
    }
    for (int i = tid; i < 16384; i += 256) Af[i] = AGG[i];
    for (int i = tid; i < 16384; i += 256) {
        int kk = i >> 7, n = i & 127;
        uint32_t off = tile_off(n, kk);
        Wf[i] = __bfloat162float(*(const __nv_bfloat16*)(wfc + off)) +
                __bfloat162float(*(const __nv_bfloat16*)(wfc + 32768 + off));
    }
    __syncthreads();
    {
        int row = tid >> 1, cbb = (tid & 1) * 64;
        int grow = row0 + row;
        for (int c = 0; c < 64; c++) {
            float acc = fcb[cbb + c];
            for (int kk = 0; kk < 128; kk++) acc += Af[row * 128 + kk] * Wf[kk * 128 + cbb + c];
            acc = fmaxf(acc, 0.f);
            if (grow < NN) {
                Hout[(size_t)grow * DIM + cbb + c] = acc;
                atomicAdd(&stats_out[cbb + c], acc);
                atomicAdd(&stats_out[DIM + cbb + c], acc * acc);
            }
        }
    }
#endif
}

// ---------------- final BatchNorm normalize ----------------
__global__ void __launch_bounds__(256) k_bnnorm(const float* __restrict__ h,
                                                const float* __restrict__ stats,
                                                const float* __restrict__ gamma,
                                                const float* __restrict__ beta,
                                                float* __restrict__ out) {
    int i = blockIdx.x * 256 + threadIdx.x;
    if (i >= NN * DIM / 4) return;
    int c = (i & 31) * 4;
    float4 v = *(const float4*)(h + (size_t)i * 4);
    float vin[4] = {v.x, v.y, v.z, v.w};
    float o[4];
#pragma unroll
    for (int j = 0; j < 4; j++) {
        float mean = stats[c + j] * (1.f / NN);
        float var = stats[DIM + c + j] * (1.f / NN) - mean * mean;
        float inv = rsqrtf(var + BN_EPS);
        o[j] = (vin[j] - mean) * inv * gamma[c + j] + beta[c + j];
    }
    *(float4*)(out + (size_t)i * 4) = make_float4(o[0], o[1], o[2], o[3]);
}

// ---------------- launch ----------------
extern "C" void kernel_launch(void* const* d_in, const int* in_sizes, int n_in,
                              void* d_out, int out_size) {
    const float* x      = (const float*)d_in[0];
    const int*   edges  = (const int*)d_in[1];
    const float* conv_W = (const float*)d_in[2];
    const float* conv_b = (const float*)d_in[3];
    const float* fc_W   = (const float*)d_in[4];
    const float* fc_b   = (const float*)d_in[5];
    const float* gamma  = (const float*)d_in[6];
    const float* beta   = (const float*)d_in[7];
    float* out = (float*)d_out;

    float *hA, *hB, *t, *dinv_o, *dinv_i, *stats3, *fceff;
    int *cnt_in, *cnt_out, *cursor, *excl, *bsum, *srcidx;
    uint8_t* wbf;
    cudaGetSymbolAddress((void**)&hA, g_hA);
    cudaGetSymbolAddress((void**)&hB, g_hB);
    cudaGetSymbolAddress((void**)&t, g_t);
    cudaGetSymbolAddress((void**)&dinv_o, g_dinv_o);
    cudaGetSymbolAddress((void**)&dinv_i, g_dinv_i);
    cudaGetSymbolAddress((void**)&cnt_in, g_cnt_in);
    cudaGetSymbolAddress((void**)&cnt_out, g_cnt_out);
    cudaGetSymbolAddress((void**)&cursor, g_cursor);
    cudaGetSymbolAddress((void**)&excl, g_excl);
    cudaGetSymbolAddress((void**)&bsum, g_bsum);
    cudaGetSymbolAddress((void**)&srcidx, g_srcidx);
    cudaGetSymbolAddress((void**)&stats3, g_stats3);
    cudaGetSymbolAddress((void**)&wbf, g_Wbf);
    cudaGetSymbolAddress((void**)&fceff, g_fceff);

    cudaFuncSetAttribute(k_mm, cudaFuncAttributeMaxDynamicSharedMemorySize, M_TOTAL);

    const int NSC = NR * NN;
    const int NB1 = (NSC + 1023) / 1024;
    const int GGRID = (NN + 7) / 8;        // warp per node, 8 warps/block
    const int MMGRID = (NN + 127) / 128;   // 782

    // ---- prep ----
    k_wprep<<<(12 * 16384 + 255) / 256, 256>>>(conv_W, fc_W, wbf);
    k_bprep<<<NL, 128>>>(conv_b, fc_W, fc_b, fceff);
    k_zeroprep<<<(NSC + 255) / 256, 256>>>(cnt_in, cnt_out, cursor, stats3, NSC);
    k_cnt<<<(NR * NE + 255) / 256, 256>>>(edges, cnt_out, cnt_in);
    k_dinv<<<(NSC + 255) / 256, 256>>>(cnt_out, cnt_in, dinv_o, dinv_i);
    k_scan1<<<NB1, 1024>>>(cnt_in, excl, bsum, NSC);
    k_scan2<<<1, 512>>>(bsum, NB1);
    k_scan3<<<NB1, 1024>>>(excl, bsum, NSC);
    k_place<<<(NR * NE + 255) / 256, 256>>>(edges, excl, cursor, srcidx);

    // ---- layer 0 ----
    k_gath<false><<<GGRID, 256>>>((const float4*)x, srcidx, excl, cnt_in, dinv_o, dinv_i,
                                  nullptr, nullptr, nullptr, t);
    k_mm<<<MMGRID, 256, M_TOTAL>>>(t, wbf, wbf + (size_t)9 * 65536, fceff, hA, stats3);
    // ---- layer 1 ----
    k_gath<true><<<GGRID, 256>>>((const float4*)hA, srcidx, excl, cnt_in, dinv_o, dinv_i,
                                 stats3, gamma, beta, t);
    k_mm<<<MMGRID, 256, M_TOTAL>>>(t, wbf + (size_t)3 * 65536, wbf + (size_t)10 * 65536,
                                   fceff + DIM, hB, stats3 + 2 * DIM);
    // ---- layer 2 ----
    k_gath<true><<<GGRID, 256>>>((const float4*)hB, srcidx, excl, cnt_in, dinv_o, dinv_i,
                                 stats3 + 2 * DIM, gamma + DIM, beta + DIM, t);
    k_mm<<<MMGRID, 256, M_TOTAL>>>(t, wbf + (size_t)6 * 65536, wbf + (size_t)11 * 65536,
                                   fceff + 2 * DIM, hA, stats3 + 4 * DIM);

    k_bnnorm<<<(NN * DIM / 4 + 255) / 256, 256>>>(hA, stats3 + 4 * DIM,
                                                  gamma + 2 * DIM, beta + 2 * DIM, out);
}